// round 13
// baseline (speedup 1.0000x reference)
#include <cuda_runtime.h>
#include <cuda_fp16.h>
#include <cstdint>

#define IH 400
#define IW 400
#define NPIX 160000
#define F1 128
#define F2 64
#define F3 8

#define PW 416                 // padded image stride / height
#define CH (PW * PW)           // per-channel padded elems

// smem: h2 staging + small tables
#define OFF_H2S 0              // 4 warps x 32 px x 65 f32 = 33280 B
#define OFF_B1S 33280
#define OFF_B2S 33792
#define OFF_B3S 34048
#define OFF_W3S 34080
#define OFF_KOF 36128          // 64 x int2 = 512 B
#define SMEM_BYTES 36640

#define PAD_BLOCKS 507         // ceil((3*CH/4)/256)
#define PREP_ITEMS (12288 + 2048)

// padded input image, hi/lo fp16 packed per pixel: (hi<<16)|lo, zero border
__device__ uint32_t g_xhl[3 * CH];
// Pre-packed fp16 weight fragments (uint2 = {b0,b1} per lane)
__device__ uint2 g_B1f[3 * 4096];          // [t = chunk*8+kt][ni][lane]
__device__ uint2 g_W2f[2048];              // [kt][ni2][lane]

// ---------------- helpers ----------------
__device__ __forceinline__ uint32_t cvt2h(float hi_val, float lo_val) {
    uint32_t r;
    asm("cvt.rn.f16x2.f32 %0, %1, %2;" : "=r"(r) : "f"(hi_val), "f"(lo_val));
    return r;
}
__device__ __forceinline__ uint32_t prmt(uint32_t a, uint32_t b, uint32_t s) {
    uint32_t r;
    asm("prmt.b32 %0, %1, %2, %3;" : "=r"(r) : "r"(a), "r"(b), "r"(s));
    return r;
}
__device__ __forceinline__ float lrelu(float t) { return t > 0.f ? t : 0.01f * t; }

#define MMA(d, a, b0_, b1_) \
    asm("mma.sync.aligned.m16n8k16.row.col.f32.f16.f16.f32 " \
        "{%0,%1,%2,%3},{%4,%5,%6,%7},{%8,%9},{%0,%1,%2,%3};" \
        : "+f"((d).x), "+f"((d).y), "+f"((d).z), "+f"((d).w) \
        : "r"((a)[0]), "r"((a)[1]), "r"((a)[2]), "r"((a)[3]), "r"(b0_), "r"(b1_))

// ---------------------------------------------------------------------------
// Prep (merged): pads x into g_xhl AND packs W1/W2 fragments (fp16).
// Blocks [0, PAD_BLOCKS) do the image; the rest do weights.
// ---------------------------------------------------------------------------
__global__ void prep_all_k(const float* __restrict__ x,
                           const float* __restrict__ W1,
                           const float* __restrict__ W2)
{
    if (blockIdx.x < PAD_BLOCKS) {
        int i4 = blockIdx.x * 256 + threadIdx.x;
        if (i4 >= 3 * CH / 4) return;
        int i = i4 * 4;
        int c = i / CH, rem = i - c * CH;
        int gy = rem / PW, gx0 = rem - gy * PW;
        int sy = gy - 5;
        uint4 wv = make_uint4(0, 0, 0, 0);
        if ((unsigned)sy < (unsigned)IH) {
            const float* xr = x + (c * IH + sy) * IW;
            uint32_t* wp = (uint32_t*)&wv;
#pragma unroll
            for (int q = 0; q < 4; q++) {
                int sx = gx0 + q - 5;
                if ((unsigned)sx < (unsigned)IW) {
                    float v = __ldg(xr + sx);
                    __half hv = __float2half_rn(v);
                    __half lv = __float2half_rn(v - __half2float(hv));
                    wp[q] = ((uint32_t)__half_as_ushort(hv) << 16) |
                            __half_as_ushort(lv);
                }
            }
        }
        *(uint4*)(g_xhl + i) = wv;
        return;
    }

    int t = (blockIdx.x - PAD_BLOCKS) * 256 + threadIdx.x;
    if (t >= PREP_ITEMS) return;
    if (t < 12288) {
        int lane = t & 31, ni = (t >> 5) & 15, kt = (t >> 9) & 7, chunk = t >> 12;
        int c = lane & 3, g = lane >> 2;
        int n = ni * 8 + g;
        int k0 = kt * 16 + 2 * c;
        float v00 = 0.f, v01 = 0.f, v10 = 0.f, v11 = 0.f;
        if (k0 + 1 < 121) {
            v00 = W1[(chunk * 121 + k0) * F1 + n];
            v01 = W1[(chunk * 121 + k0 + 1) * F1 + n];
        } else if (k0 < 121) {
            v00 = W1[(chunk * 121 + k0) * F1 + n];
        }
        if (k0 + 9 < 121) {
            v10 = W1[(chunk * 121 + k0 + 8) * F1 + n];
            v11 = W1[(chunk * 121 + k0 + 9) * F1 + n];
        } else if (k0 + 8 < 121) {
            v10 = W1[(chunk * 121 + k0 + 8) * F1 + n];
        }
        uint2 o;
        o.x = cvt2h(v01, v00);
        o.y = cvt2h(v11, v10);
        g_B1f[t] = o;
    } else {
        int t2 = t - 12288;
        int lane = t2 & 31, ni2 = (t2 >> 5) & 7, kt = t2 >> 8;
        int c = lane & 3, g = lane >> 2;
        int n = ni2 * 8 + g;
        int k0 = kt * 16 + 2 * c;
        uint2 o;
        o.x = cvt2h(W2[(k0 + 1) * F2 + n], W2[k0 * F2 + n]);
        o.y = cvt2h(W2[(k0 + 9) * F2 + n], W2[(k0 + 8) * F2 + n]);
        g_W2f[t2] = o;
    }
}

// ---------------------------------------------------------------------------
// Main: CTA = 128 px, 4 warps x 32 px. Single-fp16 x and h (residuals
// dropped): 896 MMAs/warp. x loads software-pipelined one iteration ahead.
// ---------------------------------------------------------------------------
__global__ void __launch_bounds__(128) main_k(const float* __restrict__ b1,
                                              const float* __restrict__ b2,
                                              const float* __restrict__ b3,
                                              const float* __restrict__ W3,
                                              float* __restrict__ out)
{
    extern __shared__ char smem[];
    float* sb1 = (float*)(smem + OFF_B1S);
    float* sb2 = (float*)(smem + OFF_B2S);
    float* sb3 = (float*)(smem + OFF_B3S);
    float* sW3 = (float*)(smem + OFF_W3S);
    int2*  kof = (int2*)(smem + OFF_KOF);

    const int tid = threadIdx.x;
    const int w = tid >> 5;
    const int lane = tid & 31;
    const int c4 = lane & 3, g = lane >> 2;

    if (tid < F1) sb1[tid] = b1[tid];
    if (tid < F2) sb2[tid] = b2[tid];
    if (tid < F3) sb3[tid] = b3[tid];
    for (int i = tid; i < F2 * F3; i += 128) sW3[i] = W3[i];
    if (tid < 64) {                       // k -> padded-image offset table
        int k0 = 2 * tid, k1 = 2 * tid + 1;
        kof[tid] = make_int2((k0 / 11) * PW + (k0 % 11),
                             (k1 / 11) * PW + (k1 % 11));
    }
    __syncthreads();   // only block-wide sync

    // 4 pixel base offsets for this lane: rows g, g+8 in mi=0 / mi=1 tiles
    int pbase[2][2];
#pragma unroll
    for (int mi = 0; mi < 2; mi++)
#pragma unroll
        for (int rr = 0; rr < 2; rr++) {
            int p = blockIdx.x * 128 + w * 32 + mi * 16 + rr * 8 + g;
            int py = p / IW;
            pbase[mi][rr] = py * PW + (p - py * IW);
        }

    // x-load for flattened iteration t = chunk*8 + kt (16 u32 per lane)
    auto ldx16 = [&](int t, uint32_t xr[16]) {
        const uint32_t* xc = g_xhl + (t >> 3) * CH;
        int kt = t & 7;
#pragma unroll
        for (int j = 0; j < 2; j++) {
            int2 off = kof[(kt << 3) + c4 + 4 * j];
#pragma unroll
            for (int mi = 0; mi < 2; mi++) {
                xr[j * 8 + mi * 4 + 0] = __ldg(xc + pbase[mi][0] + off.x);
                xr[j * 8 + mi * 4 + 1] = __ldg(xc + pbase[mi][0] + off.y);
                xr[j * 8 + mi * 4 + 2] = __ldg(xc + pbase[mi][1] + off.x);
                xr[j * 8 + mi * 4 + 3] = __ldg(xc + pbase[mi][1] + off.y);
            }
        }
    };

    float4 d1[2][16];
#pragma unroll
    for (int mi = 0; mi < 2; mi++)
#pragma unroll
        for (int ni = 0; ni < 16; ni++) d1[mi][ni] = make_float4(0.f, 0.f, 0.f, 0.f);

    // ================= layer 1: 24 flattened (chunk,kt) iterations =========
    uint32_t xr[16];
    ldx16(0, xr);
#pragma unroll 1
    for (int t = 0; t < 24; t++) {
        // consume prefetched x into fragments (fp16-hi pair extract)
        uint32_t ah[2][4];
#pragma unroll
        for (int j = 0; j < 2; j++)
#pragma unroll
            for (int mi = 0; mi < 2; mi++) {
                ah[mi][2 * j]     = prmt(xr[j * 8 + mi * 4 + 0],
                                         xr[j * 8 + mi * 4 + 1], 0x7632u);
                ah[mi][2 * j + 1] = prmt(xr[j * 8 + mi * 4 + 2],
                                         xr[j * 8 + mi * 4 + 3], 0x7632u);
            }

        // prefetch next iteration's x (lands under the MMAs below)
        int tn = (t < 23) ? t + 1 : 0;
        ldx16(tn, xr);

        const uint2* bp = g_B1f + (t * 16) * 32 + lane;
#pragma unroll
        for (int ni = 0; ni < 16; ni++) {
            uint2 bb = __ldg(bp + ni * 32);
            MMA(d1[0][ni], ah[0], bb.x, bb.y);
            MMA(d1[1][ni], ah[1], bb.x, bb.y);
        }
    }

    // ============ layer 2: bias+leaky+fp16 in regs, mma 128->64 ============
    float4 d2[2][8];
#pragma unroll
    for (int mi = 0; mi < 2; mi++)
#pragma unroll
        for (int ni = 0; ni < 8; ni++) d2[mi][ni] = make_float4(0.f, 0.f, 0.f, 0.f);

#pragma unroll
    for (int kt = 0; kt < 8; kt++) {
        uint32_t ah[2][4];
#pragma unroll
        for (int half = 0; half < 2; half++) {
            int ni = 2 * kt + half;
            float2 bb = *(const float2*)&sb1[8 * ni + 2 * c4];
#pragma unroll
            for (int mi = 0; mi < 2; mi++) {
                float4 D = d1[mi][ni];
                ah[mi][half * 2]     = cvt2h(lrelu(D.y + bb.y), lrelu(D.x + bb.x));
                ah[mi][half * 2 + 1] = cvt2h(lrelu(D.w + bb.y), lrelu(D.z + bb.x));
            }
        }
        const uint2* wp = g_W2f + (kt * 8) * 32 + lane;
#pragma unroll
        for (int ni = 0; ni < 8; ni++) {
            uint2 ww = __ldg(wp + ni * 32);
            MMA(d2[0][ni], ah[0], ww.x, ww.y);
            MMA(d2[1][ni], ah[1], ww.x, ww.y);
        }
    }

    // ============ h2 -> padded smem, per-pixel 64->8 + normalize ===========
    float* h2s = (float*)(smem + OFF_H2S) + w * (32 * 65);
#pragma unroll
    for (int ni = 0; ni < 8; ni++) {
        float2 bb = *(const float2*)&sb2[8 * ni + 2 * c4];
        int ch = 8 * ni + 2 * c4;
#pragma unroll
        for (int mi = 0; mi < 2; mi++) {
            float4 D = d2[mi][ni];
            int r0 = 16 * mi + g;
            h2s[r0 * 65 + ch]           = lrelu(D.x + bb.x);
            h2s[r0 * 65 + ch + 1]       = lrelu(D.y + bb.y);
            h2s[(r0 + 8) * 65 + ch]     = lrelu(D.z + bb.x);
            h2s[(r0 + 8) * 65 + ch + 1] = lrelu(D.w + bb.y);
        }
    }
    __syncwarp();

    const float* myrow = h2s + lane * 65;
    float v[F3];
#pragma unroll
    for (int e = 0; e < F3; e++) v[e] = sb3[e];
#pragma unroll 8
    for (int k = 0; k < F2; k++) {
        float hk = myrow[k];
        const float4* wr = (const float4*)&sW3[k * F3];
        float4 w0 = wr[0], w1 = wr[1];
        v[0] += hk * w0.x; v[1] += hk * w0.y; v[2] += hk * w0.z; v[3] += hk * w0.w;
        v[4] += hk * w1.x; v[5] += hk * w1.y; v[6] += hk * w1.z; v[7] += hk * w1.w;
    }
    float ss = 0.f;
#pragma unroll
    for (int e = 0; e < F3; e++) ss += v[e] * v[e];
    float inv = 1.0f / fmaxf(sqrtf(ss), 1e-12f);

    const int p = blockIdx.x * 128 + w * 32 + lane;
    float4* o = (float4*)(out + (size_t)p * F3);
    float4 o0, o1;
    o0.x = v[0] * inv; o0.y = v[1] * inv; o0.z = v[2] * inv; o0.w = v[3] * inv;
    o1.x = v[4] * inv; o1.y = v[5] * inv; o1.z = v[6] * inv; o1.w = v[7] * inv;
    o[0] = o0; o[1] = o1;
}

// ---------------------------------------------------------------------------
extern "C" void kernel_launch(void* const* d_in, const int* in_sizes, int n_in,
                              void* d_out, int out_size)
{
    const float* x  = (const float*)d_in[0];
    const float* W1 = (const float*)d_in[1];
    const float* b1 = (const float*)d_in[2];
    const float* W2 = (const float*)d_in[3];
    const float* b2 = (const float*)d_in[4];
    const float* W3 = (const float*)d_in[5];
    const float* b3 = (const float*)d_in[6];
    float* out = (float*)d_out;

    int prep_blocks = PAD_BLOCKS + (PREP_ITEMS + 255) / 256;
    prep_all_k<<<prep_blocks, 256>>>(x, W1, W2);

    cudaFuncSetAttribute(main_k, cudaFuncAttributeMaxDynamicSharedMemorySize,
                         SMEM_BYTES);
    main_k<<<NPIX / 128, 128, SMEM_BYTES>>>(b1, b2, b3, W3, out);
}

// round 14
// speedup vs baseline: 1.6628x; 1.6628x over previous
#include <cuda_runtime.h>
#include <cuda_fp16.h>
#include <cstdint>

#define IH 400
#define IW 400
#define NPIX 160000
#define F1 128
#define F2 64
#define F3 8

#define PW 416                 // padded image stride / height
#define CH (PW * PW)           // per-channel padded elems

// smem: h2 staging + small tables
#define OFF_H2S 0              // 4 warps x 32 px x 65 f32 = 33280 B
#define OFF_B1S 33280
#define OFF_B2S 33792
#define OFF_B3S 34048
#define OFF_W3S 34080
#define OFF_KOF 36128          // 64 x int2 = 512 B
#define SMEM_BYTES 36640

#define PAD_BLOCKS 507         // ceil((3*CH/4)/256)
#define PREP_ITEMS (12288 + 2048)

// padded input image, hi/lo fp16 packed per pixel: (hi<<16)|lo, zero border
__device__ uint32_t g_xhl[3 * CH];
// fp16 B fragments, ni-PAIRED for uint4 loads:
//   B1: [t][q=ni>>1][lane][half=ni&1] as uint2 -> uint4 index (t*8+q)*32+lane
__device__ uint2 g_B1f[3 * 4096];
//   W2: [kt][q=ni2>>1][lane][half] -> uint4 index (kt*4+q)*32+lane
__device__ uint2 g_W2f[2048];

// ---------------- helpers ----------------
__device__ __forceinline__ uint32_t cvt2h(float hi_val, float lo_val) {
    uint32_t r;
    asm("cvt.rn.f16x2.f32 %0, %1, %2;" : "=r"(r) : "f"(hi_val), "f"(lo_val));
    return r;
}
__device__ __forceinline__ uint32_t prmt(uint32_t a, uint32_t b, uint32_t s) {
    uint32_t r;
    asm("prmt.b32 %0, %1, %2, %3;" : "=r"(r) : "r"(a), "r"(b), "r"(s));
    return r;
}
__device__ __forceinline__ float lrelu(float t) { return t > 0.f ? t : 0.01f * t; }

#define MMA(d, a, b0_, b1_) \
    asm("mma.sync.aligned.m16n8k16.row.col.f32.f16.f16.f32 " \
        "{%0,%1,%2,%3},{%4,%5,%6,%7},{%8,%9},{%0,%1,%2,%3};" \
        : "+f"((d).x), "+f"((d).y), "+f"((d).z), "+f"((d).w) \
        : "r"((a)[0]), "r"((a)[1]), "r"((a)[2]), "r"((a)[3]), "r"(b0_), "r"(b1_))

// ---------------------------------------------------------------------------
// Prep (merged): pads x into g_xhl AND packs W1/W2 fragments (fp16, ni-paired)
// ---------------------------------------------------------------------------
__global__ void prep_all_k(const float* __restrict__ x,
                           const float* __restrict__ W1,
                           const float* __restrict__ W2)
{
    if (blockIdx.x < PAD_BLOCKS) {
        int i4 = blockIdx.x * 256 + threadIdx.x;
        if (i4 >= 3 * CH / 4) return;
        int i = i4 * 4;
        int c = i / CH, rem = i - c * CH;
        int gy = rem / PW, gx0 = rem - gy * PW;
        int sy = gy - 5;
        uint4 wv = make_uint4(0, 0, 0, 0);
        if ((unsigned)sy < (unsigned)IH) {
            const float* xr = x + (c * IH + sy) * IW;
            uint32_t* wp = (uint32_t*)&wv;
#pragma unroll
            for (int q = 0; q < 4; q++) {
                int sx = gx0 + q - 5;
                if ((unsigned)sx < (unsigned)IW) {
                    float v = __ldg(xr + sx);
                    __half hv = __float2half_rn(v);
                    __half lv = __float2half_rn(v - __half2float(hv));
                    wp[q] = ((uint32_t)__half_as_ushort(hv) << 16) |
                            __half_as_ushort(lv);
                }
            }
        }
        *(uint4*)(g_xhl + i) = wv;
        return;
    }

    int t = (blockIdx.x - PAD_BLOCKS) * 256 + threadIdx.x;
    if (t >= PREP_ITEMS) return;
    if (t < 12288) {
        int lane = t & 31, ni = (t >> 5) & 15, kt = (t >> 9) & 7, chunk = t >> 12;
        int c = lane & 3, g = lane >> 2;
        int n = ni * 8 + g;
        int k0 = kt * 16 + 2 * c;
        float v00 = 0.f, v01 = 0.f, v10 = 0.f, v11 = 0.f;
        if (k0 + 1 < 121) {
            v00 = W1[(chunk * 121 + k0) * F1 + n];
            v01 = W1[(chunk * 121 + k0 + 1) * F1 + n];
        } else if (k0 < 121) {
            v00 = W1[(chunk * 121 + k0) * F1 + n];
        }
        if (k0 + 9 < 121) {
            v10 = W1[(chunk * 121 + k0 + 8) * F1 + n];
            v11 = W1[(chunk * 121 + k0 + 9) * F1 + n];
        } else if (k0 + 8 < 121) {
            v10 = W1[(chunk * 121 + k0 + 8) * F1 + n];
        }
        uint2 o;
        o.x = cvt2h(v01, v00);
        o.y = cvt2h(v11, v10);
        int tf = (chunk << 3) + kt;
        g_B1f[(((tf << 3) + (ni >> 1)) * 32 + lane) * 2 + (ni & 1)] = o;
    } else {
        int t2 = t - 12288;
        int lane = t2 & 31, ni2 = (t2 >> 5) & 7, kt = t2 >> 8;
        int c = lane & 3, g = lane >> 2;
        int n = ni2 * 8 + g;
        int k0 = kt * 16 + 2 * c;
        uint2 o;
        o.x = cvt2h(W2[(k0 + 1) * F2 + n], W2[k0 * F2 + n]);
        o.y = cvt2h(W2[(k0 + 9) * F2 + n], W2[(k0 + 8) * F2 + n]);
        g_W2f[(((kt << 2) + (ni2 >> 1)) * 32 + lane) * 2 + (ni2 & 1)] = o;
    }
}

// ---------------------------------------------------------------------------
// Main: CTA = 128 px, 4 warps x 32 px. fp16-single MMAs (896/warp); BOTH x and
// B-fragment loads software-pipelined one iteration ahead (B ping-pong uint4).
// ---------------------------------------------------------------------------
__global__ void __launch_bounds__(128) main_k(const float* __restrict__ b1,
                                              const float* __restrict__ b2,
                                              const float* __restrict__ b3,
                                              const float* __restrict__ W3,
                                              float* __restrict__ out)
{
    extern __shared__ char smem[];
    float* sb1 = (float*)(smem + OFF_B1S);
    float* sb2 = (float*)(smem + OFF_B2S);
    float* sb3 = (float*)(smem + OFF_B3S);
    float* sW3 = (float*)(smem + OFF_W3S);
    int2*  kof = (int2*)(smem + OFF_KOF);

    const int tid = threadIdx.x;
    const int w = tid >> 5;
    const int lane = tid & 31;
    const int c4 = lane & 3, g = lane >> 2;

    if (tid < F1) sb1[tid] = b1[tid];
    if (tid < F2) sb2[tid] = b2[tid];
    if (tid < F3) sb3[tid] = b3[tid];
    for (int i = tid; i < F2 * F3; i += 128) sW3[i] = W3[i];
    if (tid < 64) {                       // k -> padded-image offset table
        int k0 = 2 * tid, k1 = 2 * tid + 1;
        kof[tid] = make_int2((k0 / 11) * PW + (k0 % 11),
                             (k1 / 11) * PW + (k1 % 11));
    }
    __syncthreads();   // only block-wide sync

    int pbase[2][2];
#pragma unroll
    for (int mi = 0; mi < 2; mi++)
#pragma unroll
        for (int rr = 0; rr < 2; rr++) {
            int p = blockIdx.x * 128 + w * 32 + mi * 16 + rr * 8 + g;
            int py = p / IW;
            pbase[mi][rr] = py * PW + (p - py * IW);
        }

    // x-load for flattened iteration t (16 u32 per lane)
    auto ldx16 = [&](int t, uint32_t xr[16]) {
        const uint32_t* xc = g_xhl + (t >> 3) * CH;
        int kt = t & 7;
#pragma unroll
        for (int j = 0; j < 2; j++) {
            int2 off = kof[(kt << 3) + c4 + 4 * j];
#pragma unroll
            for (int mi = 0; mi < 2; mi++) {
                xr[j * 8 + mi * 4 + 0] = __ldg(xc + pbase[mi][0] + off.x);
                xr[j * 8 + mi * 4 + 1] = __ldg(xc + pbase[mi][0] + off.y);
                xr[j * 8 + mi * 4 + 2] = __ldg(xc + pbase[mi][1] + off.x);
                xr[j * 8 + mi * 4 + 3] = __ldg(xc + pbase[mi][1] + off.y);
            }
        }
    };
    // B-fragment load for iteration t: 8 x uint4
    auto ldb8 = [&](int t, uint4 bf[8]) {
        const uint4* bp = (const uint4*)g_B1f + t * 256 + lane;
#pragma unroll
        for (int q = 0; q < 8; q++) bf[q] = __ldg(bp + q * 32);
    };
    auto mkah = [&](const uint32_t xr[16], uint32_t ah[2][4]) {
#pragma unroll
        for (int j = 0; j < 2; j++)
#pragma unroll
            for (int mi = 0; mi < 2; mi++) {
                ah[mi][2 * j]     = prmt(xr[j * 8 + mi * 4 + 0],
                                         xr[j * 8 + mi * 4 + 1], 0x7632u);
                ah[mi][2 * j + 1] = prmt(xr[j * 8 + mi * 4 + 2],
                                         xr[j * 8 + mi * 4 + 3], 0x7632u);
            }
    };

    float4 d1[2][16];
#pragma unroll
    for (int mi = 0; mi < 2; mi++)
#pragma unroll
        for (int ni = 0; ni < 16; ni++) d1[mi][ni] = make_float4(0.f, 0.f, 0.f, 0.f);

    // ======== layer 1: 24 iterations, unrolled x2 with B ping-pong =========
    uint32_t xr[16];
    uint4 bA[8], bB[8];
    ldx16(0, xr);
    ldb8(0, bA);
#pragma unroll 1
    for (int t = 0; t < 24; t += 2) {
        uint32_t ah[2][4];

        // ---- iteration t (consumes bA) ----
        mkah(xr, ah);
        ldx16(t + 1, xr);          // prefetch x for t+1
        ldb8(t + 1, bB);           // prefetch B for t+1 (lands under MMAs)
#pragma unroll
        for (int q = 0; q < 8; q++) {
            MMA(d1[0][2 * q],     ah[0], bA[q].x, bA[q].y);
            MMA(d1[1][2 * q],     ah[1], bA[q].x, bA[q].y);
            MMA(d1[0][2 * q + 1], ah[0], bA[q].z, bA[q].w);
            MMA(d1[1][2 * q + 1], ah[1], bA[q].z, bA[q].w);
        }

        // ---- iteration t+1 (consumes bB) ----
        int tn = (t + 2 < 24) ? t + 2 : 0;
        mkah(xr, ah);
        ldx16(tn, xr);
        ldb8(tn, bA);
#pragma unroll
        for (int q = 0; q < 8; q++) {
            MMA(d1[0][2 * q],     ah[0], bB[q].x, bB[q].y);
            MMA(d1[1][2 * q],     ah[1], bB[q].x, bB[q].y);
            MMA(d1[0][2 * q + 1], ah[0], bB[q].z, bB[q].w);
            MMA(d1[1][2 * q + 1], ah[1], bB[q].z, bB[q].w);
        }
    }

    // ============ layer 2: bias+leaky+fp16 in regs, mma 128->64 ============
    float4 d2[2][8];
#pragma unroll
    for (int mi = 0; mi < 2; mi++)
#pragma unroll
        for (int ni = 0; ni < 8; ni++) d2[mi][ni] = make_float4(0.f, 0.f, 0.f, 0.f);

#pragma unroll
    for (int kt = 0; kt < 8; kt++) {
        uint32_t ah[2][4];
#pragma unroll
        for (int half = 0; half < 2; half++) {
            int ni = 2 * kt + half;
            float2 bb = *(const float2*)&sb1[8 * ni + 2 * c4];
#pragma unroll
            for (int mi = 0; mi < 2; mi++) {
                float4 D = d1[mi][ni];
                ah[mi][half * 2]     = cvt2h(lrelu(D.y + bb.y), lrelu(D.x + bb.x));
                ah[mi][half * 2 + 1] = cvt2h(lrelu(D.w + bb.y), lrelu(D.z + bb.x));
            }
        }
        const uint4* wp = (const uint4*)g_W2f + kt * 128 + lane;
#pragma unroll
        for (int q = 0; q < 4; q++) {
            uint4 ww = __ldg(wp + q * 32);
            MMA(d2[0][2 * q],     ah[0], ww.x, ww.y);
            MMA(d2[1][2 * q],     ah[1], ww.x, ww.y);
            MMA(d2[0][2 * q + 1], ah[0], ww.z, ww.w);
            MMA(d2[1][2 * q + 1], ah[1], ww.z, ww.w);
        }
    }

    // ============ h2 -> padded smem, per-pixel 64->8 + normalize ===========
    float* h2s = (float*)(smem + OFF_H2S) + w * (32 * 65);
#pragma unroll
    for (int ni = 0; ni < 8; ni++) {
        float2 bb = *(const float2*)&sb2[8 * ni + 2 * c4];
        int ch = 8 * ni + 2 * c4;
#pragma unroll
        for (int mi = 0; mi < 2; mi++) {
            float4 D = d2[mi][ni];
            int r0 = 16 * mi + g;
            h2s[r0 * 65 + ch]           = lrelu(D.x + bb.x);
            h2s[r0 * 65 + ch + 1]       = lrelu(D.y + bb.y);
            h2s[(r0 + 8) * 65 + ch]     = lrelu(D.z + bb.x);
            h2s[(r0 + 8) * 65 + ch + 1] = lrelu(D.w + bb.y);
        }
    }
    __syncwarp();

    const float* myrow = h2s + lane * 65;
    float v[F3];
#pragma unroll
    for (int e = 0; e < F3; e++) v[e] = sb3[e];
#pragma unroll 8
    for (int k = 0; k < F2; k++) {
        float hk = myrow[k];
        const float4* wr = (const float4*)&sW3[k * F3];
        float4 w0 = wr[0], w1 = wr[1];
        v[0] += hk * w0.x; v[1] += hk * w0.y; v[2] += hk * w0.z; v[3] += hk * w0.w;
        v[4] += hk * w1.x; v[5] += hk * w1.y; v[6] += hk * w1.z; v[7] += hk * w1.w;
    }
    float ss = 0.f;
#pragma unroll
    for (int e = 0; e < F3; e++) ss += v[e] * v[e];
    float inv = 1.0f / fmaxf(sqrtf(ss), 1e-12f);

    const int p = blockIdx.x * 128 + w * 32 + lane;
    float4* o = (float4*)(out + (size_t)p * F3);
    float4 o0, o1;
    o0.x = v[0] * inv; o0.y = v[1] * inv; o0.z = v[2] * inv; o0.w = v[3] * inv;
    o1.x = v[4] * inv; o1.y = v[5] * inv; o1.z = v[6] * inv; o1.w = v[7] * inv;
    o[0] = o0; o[1] = o1;
}

// ---------------------------------------------------------------------------
extern "C" void kernel_launch(void* const* d_in, const int* in_sizes, int n_in,
                              void* d_out, int out_size)
{
    const float* x  = (const float*)d_in[0];
    const float* W1 = (const float*)d_in[1];
    const float* b1 = (const float*)d_in[2];
    const float* W2 = (const float*)d_in[3];
    const float* b2 = (const float*)d_in[4];
    const float* W3 = (const float*)d_in[5];
    const float* b3 = (const float*)d_in[6];
    float* out = (float*)d_out;

    int prep_blocks = PAD_BLOCKS + (PREP_ITEMS + 255) / 256;
    prep_all_k<<<prep_blocks, 256>>>(x, W1, W2);

    cudaFuncSetAttribute(main_k, cudaFuncAttributeMaxDynamicSharedMemorySize,
                         SMEM_BYTES);
    main_k<<<NPIX / 128, 128, SMEM_BYTES>>>(b1, b2, b3, W3, out);
}

// round 15
// speedup vs baseline: 1.8691x; 1.1241x over previous
#include <cuda_runtime.h>
#include <cuda_fp16.h>
#include <cstdint>

#define IH 400
#define IW 400
#define NPIX 160000
#define F1 128
#define F2 64
#define F3 8

#define PW 416                 // padded image stride / height
#define CH (PW * PW)           // per-channel padded elems (even)
#define NSTEP 25               // k-steps: 396 permuted slots (363 real) + pad

// smem: h2 staging + small tables
#define OFF_H2S 0              // 4 warps x 32 px x 65 f32 = 33280 B
#define OFF_B1S 33280
#define OFF_B2S 33792
#define OFF_B3S 34048
#define OFF_W3S 34080
#define OFF_KOF 36128          // 200 ints = 800 B
#define SMEM_BYTES 36928

#define NPADW (3 * CH / 8)     // 64896 thread-groups for image build
#define PAD_BLOCKS ((NPADW + 255) / 256)          // 254
#define PREP_ITEMS (NSTEP * 16 * 32 + 2048)       // 12800 B1 + 2048 W2

// two fp16 images (u16 values), img1 shifted by one pixel; packed as u32 pairs
__device__ uint4 g_x0[3 * CH / 8];
__device__ uint4 g_x1[3 * CH / 8];
// fp16 B fragments, ni-paired for uint4 loads: uint4 index (t*8+q)*32+lane
__device__ uint2 g_B1f[NSTEP * 16 * 32];
__device__ uint2 g_W2f[2048];

// ---------------- helpers ----------------
__device__ __forceinline__ uint32_t cvt2h(float hi_val, float lo_val) {
    uint32_t r;
    asm("cvt.rn.f16x2.f32 %0, %1, %2;" : "=r"(r) : "f"(hi_val), "f"(lo_val));
    return r;
}
__device__ __forceinline__ float lrelu(float t) { return t > 0.f ? t : 0.01f * t; }

#define MMA(d, a, b0_, b1_) \
    asm("mma.sync.aligned.m16n8k16.row.col.f32.f16.f16.f32 " \
        "{%0,%1,%2,%3},{%4,%5,%6,%7},{%8,%9},{%0,%1,%2,%3};" \
        : "+f"((d).x), "+f"((d).y), "+f"((d).z), "+f"((d).w) \
        : "r"((a)[0]), "r"((a)[1]), "r"((a)[2]), "r"((a)[3]), "r"(b0_), "r"(b1_))

// K-permutation: slot s (0..399) -> weight & x-offset.
// pair pi = s>>1: row r = pi/6 (c = r/11, ki = r%11), m = pi%6, kj = 2m + (s&1).
// Valid iff pi < 198 && kj < 11; x pair base offset (u16) = c*CH + ki*PW + 2m.
__device__ __forceinline__ float w1_slot(const float* W1, int s, int n) {
    int pi = s >> 1;
    if (pi >= 198) return 0.f;
    int r = pi / 6, m = pi - 6 * r;
    int kj = 2 * m + (s & 1);
    if (kj >= 11) return 0.f;
    int c = r / 11, ki = r - 11 * c;
    return W1[(c * 121 + ki * 11 + kj) * F1 + n];
}

// ---------------------------------------------------------------------------
// Prep: build both fp16 images + pack W1/W2 fragments
// ---------------------------------------------------------------------------
__global__ void prep_all_k(const float* __restrict__ x,
                           const float* __restrict__ W1,
                           const float* __restrict__ W2)
{
    if (blockIdx.x < PAD_BLOCKS) {
        int b = blockIdx.x * 256 + threadIdx.x;
        if (b >= NPADW) return;
        int ub = b * 8;                       // u16 base index (row-aligned: PW%8==0)
        int c = ub / CH;
        int rem = ub - c * CH;
        int gy = rem / PW, gx0 = rem - gy * PW;
        int sy = gy - 5;
        unsigned short v[9];
        const float* xr = x + (c * IH + sy) * IW;
#pragma unroll
        for (int k = 0; k < 8; k++) {
            float val = 0.f;
            int sx = gx0 + k - 5;
            if ((unsigned)sy < (unsigned)IH && (unsigned)sx < (unsigned)IW)
                val = __ldg(xr + sx);
            v[k] = __half_as_ushort(__float2half_rn(val));
        }
        {   // v[8]: next u16 position (may wrap row/channel or run off the end)
            float val = 0.f;
            int u = ub + 8;
            if (u < 3 * CH) {
                int c8 = u / CH;
                int r8 = u - c8 * CH;
                int gy8 = r8 / PW, gx8 = r8 - gy8 * PW;
                int sy8 = gy8 - 5, sx8 = gx8 - 5;
                if ((unsigned)sy8 < (unsigned)IH && (unsigned)sx8 < (unsigned)IW)
                    val = __ldg(x + (c8 * IH + sy8) * IW + sx8);
            }
            v[8] = __half_as_ushort(__float2half_rn(val));
        }
        uint4 w0, w1v;
        w0.x = (uint32_t)v[0] | ((uint32_t)v[1] << 16);
        w0.y = (uint32_t)v[2] | ((uint32_t)v[3] << 16);
        w0.z = (uint32_t)v[4] | ((uint32_t)v[5] << 16);
        w0.w = (uint32_t)v[6] | ((uint32_t)v[7] << 16);
        w1v.x = (uint32_t)v[1] | ((uint32_t)v[2] << 16);
        w1v.y = (uint32_t)v[3] | ((uint32_t)v[4] << 16);
        w1v.z = (uint32_t)v[5] | ((uint32_t)v[6] << 16);
        w1v.w = (uint32_t)v[7] | ((uint32_t)v[8] << 16);
        g_x0[b] = w0;
        g_x1[b] = w1v;
        return;
    }

    int t = (blockIdx.x - PAD_BLOCKS) * 256 + threadIdx.x;
    if (t >= PREP_ITEMS) return;
    if (t < NSTEP * 16 * 32) {
        int lane = t & 31, ni = (t >> 5) & 15, it = t >> 9;   // it 0..24
        int c = lane & 3, g = lane >> 2;
        int n = ni * 8 + g;
        int s0 = it * 16 + 2 * c;          // b0 pair slots (s0, s0+1)
        int s1 = s0 + 8;                   // b1 pair slots
        uint2 o;
        o.x = cvt2h(w1_slot(W1, s0 + 1, n), w1_slot(W1, s0, n));
        o.y = cvt2h(w1_slot(W1, s1 + 1, n), w1_slot(W1, s1, n));
        g_B1f[(((it << 3) + (ni >> 1)) * 32 + lane) * 2 + (ni & 1)] = o;
    } else {
        int t2 = t - NSTEP * 16 * 32;
        int lane = t2 & 31, ni2 = (t2 >> 5) & 7, kt = t2 >> 8;
        int c = lane & 3, g = lane >> 2;
        int n = ni2 * 8 + g;
        int k0 = kt * 16 + 2 * c;
        uint2 o;
        o.x = cvt2h(W2[(k0 + 1) * F2 + n], W2[k0 * F2 + n]);
        o.y = cvt2h(W2[(k0 + 9) * F2 + n], W2[(k0 + 8) * F2 + n]);
        g_W2f[(((kt << 2) + (ni2 >> 1)) * 32 + lane) * 2 + (ni2 & 1)] = o;
    }
}

// ---------------------------------------------------------------------------
// Main: CTA = 128 px, 4 warps x 32 px. Each A-fragment register is ONE aligned
// LDG.32 (fp16 pair) thanks to the K-permutation + dual shifted images.
// x and B double-buffered across the 25 k-steps.
// ---------------------------------------------------------------------------
__global__ void __launch_bounds__(128) main_k(const float* __restrict__ b1,
                                              const float* __restrict__ b2,
                                              const float* __restrict__ b3,
                                              const float* __restrict__ W3,
                                              float* __restrict__ out)
{
    extern __shared__ char smem[];
    float* sb1 = (float*)(smem + OFF_B1S);
    float* sb2 = (float*)(smem + OFF_B2S);
    float* sb3 = (float*)(smem + OFF_B3S);
    float* sW3 = (float*)(smem + OFF_W3S);
    int*   skof = (int*)(smem + OFF_KOF);

    const int tid = threadIdx.x;
    const int w = tid >> 5;
    const int lane = tid & 31;
    const int c4 = lane & 3, g = lane >> 2;

    if (tid < F1) sb1[tid] = b1[tid];
    if (tid < F2) sb2[tid] = b2[tid];
    if (tid < F3) sb3[tid] = b3[tid];
    for (int i = tid; i < F2 * F3; i += 128) sW3[i] = W3[i];
    for (int i = tid; i < 200; i += 128) {   // pair pi -> u32 x-offset
        int pi = i;
        int off = 0;
        if (pi < 198) {
            int r = pi / 6, m = pi - 6 * r;
            int c = r / 11, ki = r - 11 * c;
            off = (c * CH + ki * PW + 2 * m) >> 1;
        }
        skof[i] = off;
    }
    __syncthreads();   // only block-wide sync

    // 4 per-lane base pointers (mi,rr), parity-resolved once
    const uint32_t* x0 = (const uint32_t*)g_x0;
    const uint32_t* x1 = (const uint32_t*)g_x1;
    const uint32_t* bptr[4];
#pragma unroll
    for (int mi = 0; mi < 2; mi++)
#pragma unroll
        for (int rr = 0; rr < 2; rr++) {
            int p = blockIdx.x * 128 + w * 32 + mi * 16 + rr * 8 + g;
            int py = p / IW;
            int pb = py * PW + (p - py * IW);
            bptr[mi * 2 + rr] = (pb & 1) ? (x1 + ((pb - 1) >> 1))
                                         : (x0 + (pb >> 1));
        }

    // A-fragment loads for k-step t: 8 LDG.32, each IS a fragment register
    auto ldx8 = [&](int t, uint32_t xf[8]) {
        int o0 = skof[t * 8 + c4];
        int o1 = skof[t * 8 + 4 + c4];
        xf[0] = __ldg(bptr[0] + o0);   // mi0 rr0 j0
        xf[1] = __ldg(bptr[1] + o0);   // mi0 rr1 j0
        xf[2] = __ldg(bptr[0] + o1);   // mi0 rr0 j1
        xf[3] = __ldg(bptr[1] + o1);   // mi0 rr1 j1
        xf[4] = __ldg(bptr[2] + o0);   // mi1 ...
        xf[5] = __ldg(bptr[3] + o0);
        xf[6] = __ldg(bptr[2] + o1);
        xf[7] = __ldg(bptr[3] + o1);
    };
    auto ldb8 = [&](int t, uint4 bf[8]) {
        const uint4* bp = (const uint4*)g_B1f + t * 256 + lane;
#pragma unroll
        for (int q = 0; q < 8; q++) bf[q] = __ldg(bp + q * 32);
    };

    float4 d1[2][16];
#pragma unroll
    for (int mi = 0; mi < 2; mi++)
#pragma unroll
        for (int ni = 0; ni < 16; ni++) d1[mi][ni] = make_float4(0.f, 0.f, 0.f, 0.f);

    auto domma = [&](const uint32_t* xf, const uint4* bf) {
#pragma unroll
        for (int q = 0; q < 8; q++) {
            MMA(d1[0][2 * q],     xf,     bf[q].x, bf[q].y);
            MMA(d1[1][2 * q],     xf + 4, bf[q].x, bf[q].y);
            MMA(d1[0][2 * q + 1], xf,     bf[q].z, bf[q].w);
            MMA(d1[1][2 * q + 1], xf + 4, bf[q].z, bf[q].w);
        }
    };

    // ======== layer 1: 25 k-steps, x2 unrolled with double buffers =========
    uint32_t xA[8], xB[8];
    uint4 bA[8], bB[8];
    ldx8(0, xA);
    ldb8(0, bA);
#pragma unroll 1
    for (int t = 0; t < 24; t += 2) {
        ldx8(t + 1, xB);
        ldb8(t + 1, bB);
        domma(xA, bA);
        ldx8(t + 2, xA);      // t+2 <= 24, always valid
        ldb8(t + 2, bA);
        domma(xB, bB);
    }
    domma(xA, bA);            // t = 24

    // ============ layer 2: bias+leaky+fp16 in regs, mma 128->64 ============
    float4 d2[2][8];
#pragma unroll
    for (int mi = 0; mi < 2; mi++)
#pragma unroll
        for (int ni = 0; ni < 8; ni++) d2[mi][ni] = make_float4(0.f, 0.f, 0.f, 0.f);

#pragma unroll
    for (int kt = 0; kt < 8; kt++) {
        uint32_t ah[2][4];
#pragma unroll
        for (int half = 0; half < 2; half++) {
            int ni = 2 * kt + half;
            float2 bb = *(const float2*)&sb1[8 * ni + 2 * c4];
#pragma unroll
            for (int mi = 0; mi < 2; mi++) {
                float4 D = d1[mi][ni];
                ah[mi][half * 2]     = cvt2h(lrelu(D.y + bb.y), lrelu(D.x + bb.x));
                ah[mi][half * 2 + 1] = cvt2h(lrelu(D.w + bb.y), lrelu(D.z + bb.x));
            }
        }
        const uint4* wp = (const uint4*)g_W2f + kt * 128 + lane;
#pragma unroll
        for (int q = 0; q < 4; q++) {
            uint4 ww = __ldg(wp + q * 32);
            MMA(d2[0][2 * q],     ah[0], ww.x, ww.y);
            MMA(d2[1][2 * q],     ah[1], ww.x, ww.y);
            MMA(d2[0][2 * q + 1], ah[0], ww.z, ww.w);
            MMA(d2[1][2 * q + 1], ah[1], ww.z, ww.w);
        }
    }

    // ============ h2 -> padded smem, per-pixel 64->8 + normalize ===========
    float* h2s = (float*)(smem + OFF_H2S) + w * (32 * 65);
#pragma unroll
    for (int ni = 0; ni < 8; ni++) {
        float2 bb = *(const float2*)&sb2[8 * ni + 2 * c4];
        int ch = 8 * ni + 2 * c4;
#pragma unroll
        for (int mi = 0; mi < 2; mi++) {
            float4 D = d2[mi][ni];
            int r0 = 16 * mi + g;
            h2s[r0 * 65 + ch]           = lrelu(D.x + bb.x);
            h2s[r0 * 65 + ch + 1]       = lrelu(D.y + bb.y);
            h2s[(r0 + 8) * 65 + ch]     = lrelu(D.z + bb.x);
            h2s[(r0 + 8) * 65 + ch + 1] = lrelu(D.w + bb.y);
        }
    }
    __syncwarp();

    const float* myrow = h2s + lane * 65;
    float v[F3];
#pragma unroll
    for (int e = 0; e < F3; e++) v[e] = sb3[e];
#pragma unroll 8
    for (int k = 0; k < F2; k++) {
        float hk = myrow[k];
        const float4* wr = (const float4*)&sW3[k * F3];
        float4 w0 = wr[0], w1 = wr[1];
        v[0] += hk * w0.x; v[1] += hk * w0.y; v[2] += hk * w0.z; v[3] += hk * w0.w;
        v[4] += hk * w1.x; v[5] += hk * w1.y; v[6] += hk * w1.z; v[7] += hk * w1.w;
    }
    float ss = 0.f;
#pragma unroll
    for (int e = 0; e < F3; e++) ss += v[e] * v[e];
    float inv = 1.0f / fmaxf(sqrtf(ss), 1e-12f);

    const int p = blockIdx.x * 128 + w * 32 + lane;
    float4* o = (float4*)(out + (size_t)p * F3);
    float4 o0, o1;
    o0.x = v[0] * inv; o0.y = v[1] * inv; o0.z = v[2] * inv; o0.w = v[3] * inv;
    o1.x = v[4] * inv; o1.y = v[5] * inv; o1.z = v[6] * inv; o1.w = v[7] * inv;
    o[0] = o0; o[1] = o1;
}

// ---------------------------------------------------------------------------
extern "C" void kernel_launch(void* const* d_in, const int* in_sizes, int n_in,
                              void* d_out, int out_size)
{
    const float* x  = (const float*)d_in[0];
    const float* W1 = (const float*)d_in[1];
    const float* b1 = (const float*)d_in[2];
    const float* W2 = (const float*)d_in[3];
    const float* b2 = (const float*)d_in[4];
    const float* W3 = (const float*)d_in[5];
    const float* b3 = (const float*)d_in[6];
    float* out = (float*)d_out;

    int prep_blocks = PAD_BLOCKS + (PREP_ITEMS + 255) / 256;
    prep_all_k<<<prep_blocks, 256>>>(x, W1, W2);

    cudaFuncSetAttribute(main_k, cudaFuncAttributeMaxDynamicSharedMemorySize,
                         SMEM_BYTES);
    main_k<<<NPIX / 128, 128, SMEM_BYTES>>>(b1, b2, b3, W3, out);
}